// round 4
// baseline (speedup 1.0000x reference)
#include <cuda_runtime.h>
#include <cstddef>

// x: (8, 16, 3, 256, 256) fp32; out: (128, 2, 256, 256) fp32
// out[b*16+l, ch, :] = x[b,l,0,:] - x[b,l-1,0,:] (zero at l=0), ch0 == ch1.
//
// One thread per (b, hw4) position, walking the full l chain: each input
// float4 is read from L2 exactly once (prev kept in registers), cutting L2
// traffic from 134 MB to 100 MB (the compulsory minimum).

static constexpr int HW4 = 16384;   // 256*256/4 float4 per plane
static constexpr int B   = 8;
static constexpr int L   = 16;
static constexpr int TOTALT = B * HW4;   // 131072 threads

__global__ __launch_bounds__(256) void dummyflow_chain_kernel(
    const float4* __restrict__ x, float4* __restrict__ out)
{
    int idx = blockIdx.x * blockDim.x + threadIdx.x;

    int b = idx >> 14;          // idx / HW4
    int j = idx & (HW4 - 1);    // within-plane float4 index (coalesced)

    // input plane stride between consecutive l (3 channels): 3*HW4
    // base: x[b, 0, 0, :]
    size_t ibase = (size_t)b * L * 3 * HW4 + j;
    // output: bl = b*16 + l, plane stride 2*HW4
    size_t obase = (size_t)b * L * 2 * HW4 + j;

    // l = 0: zero output
    float4 z = make_float4(0.f, 0.f, 0.f, 0.f);
    out[obase]       = z;
    out[obase + HW4] = z;

    float4 prev = x[ibase];

    #pragma unroll
    for (int l = 1; l < L; l++) {
        float4 a = x[ibase + (size_t)l * 3 * HW4];
        float4 v = make_float4(a.x - prev.x, a.y - prev.y,
                               a.z - prev.z, a.w - prev.w);
        size_t o = obase + (size_t)l * 2 * HW4;
        out[o]       = v;
        out[o + HW4] = v;
        prev = a;
    }
}

extern "C" void kernel_launch(void* const* d_in, const int* in_sizes, int n_in,
                              void* d_out, int out_size)
{
    const float4* x = (const float4*)d_in[0];
    float4* out = (float4*)d_out;

    int threads = 256;
    int blocks = TOTALT / threads;   // 512
    dummyflow_chain_kernel<<<blocks, threads>>>(x, out);
}

// round 5
// speedup vs baseline: 1.1383x; 1.1383x over previous
#include <cuda_runtime.h>
#include <cstddef>

// x: (8, 16, 3, 256, 256) fp32; out: (128, 2, 256, 256) fp32
// out[bl, ch, hw] = plane(bl*3) - plane((bl-1)*3), zero when bl%16==0; ch0==ch1.
//
// R1 layout (fully coalesced, 1 float4/thread, high occupancy) + streaming
// stores (__stcs) so the 67 MB write stream does not evict the 33.5 MB input
// working set from L2 across graph replays -> steady-state DRAM traffic
// approaches the 67 MB write-only floor.

static constexpr int HW4 = 16384;         // 256*256/4
static constexpr int BL  = 128;           // 8*16
static constexpr int TOTAL4 = BL * HW4;   // 2,097,152 float4 threads

__global__ __launch_bounds__(256) void dummyflow_diff_kernel(
    const float4* __restrict__ x, float4* __restrict__ out)
{
    int idx = blockIdx.x * blockDim.x + threadIdx.x;
    if (idx >= TOTAL4) return;

    int bl = idx >> 14;         // idx / HW4
    int hw = idx & (HW4 - 1);   // idx % HW4
    int l  = bl & 15;

    float4 v;
    if (l == 0) {
        v = make_float4(0.f, 0.f, 0.f, 0.f);
    } else {
        size_t cur  = (size_t)(bl * 3)       * HW4 + hw;
        size_t prev = (size_t)((bl - 1) * 3) * HW4 + hw;
        float4 a = __ldg(&x[cur]);
        float4 p = __ldg(&x[prev]);
        v = make_float4(a.x - p.x, a.y - p.y, a.z - p.z, a.w - p.w);
    }

    size_t o = (size_t)(bl * 2) * HW4 + hw;
    __stcs(&out[o], v);         // channel 0 — streaming (evict-first)
    __stcs(&out[o + HW4], v);   // channel 1
}

extern "C" void kernel_launch(void* const* d_in, const int* in_sizes, int n_in,
                              void* d_out, int out_size)
{
    const float4* x = (const float4*)d_in[0];
    float4* out = (float4*)d_out;

    int threads = 256;
    int blocks = (TOTAL4 + threads - 1) / threads;  // 8192
    dummyflow_diff_kernel<<<blocks, threads>>>(x, out);
}